// round 9
// baseline (speedup 1.0000x reference)
#include <cuda_runtime.h>

#define B_ROWS 16384
#define NN     128
#define NS     1024
#define GRID_MAIN 296            // 2 blocks/SM * 148 SMs
#define BLOCK_MAIN 256
#define LANES (GRID_MAIN * 2)
#define NSHARD 4

typedef unsigned long long u64;

// ---------------- scratch (device globals; statically zero-initialized) ----------------
__device__ float g_sA[NSHARD][NS];   // sum g*s*softplus(-x)  (sub, pw-weighted part)
__device__ float g_sC[NSHARD][NS];   // sum s (ungated column count)
__device__ float g_nU[NSHARD][NN];   // sum y*softplus(-x)    (narrative)
__device__ float g_nC[NSHARD][NN];   // sum y
__device__ float g_scl[8];           // 0=Qs 1=Wn 2=hier 3=nf 4=sf
__device__ unsigned int g_ctr;

// ---------------- f32x2 packed helpers (Blackwell) ----------------
__device__ __forceinline__ u64 pk2(float lo, float hi) {
    u64 r;
    asm("mov.b64 %0, {%1, %2};" : "=l"(r) : "r"(__float_as_uint(lo)), "r"(__float_as_uint(hi)));
    return r;
}
__device__ __forceinline__ void upk2(u64 v, float& lo, float& hi) {
    unsigned int a, b;
    asm("mov.b64 {%0, %1}, %2;" : "=r"(a), "=r"(b) : "l"(v));
    lo = __uint_as_float(a); hi = __uint_as_float(b);
}
__device__ __forceinline__ u64 mul2(u64 a, u64 b) {
    u64 r; asm("mul.rn.f32x2 %0, %1, %2;" : "=l"(r) : "l"(a), "l"(b)); return r;
}
__device__ __forceinline__ u64 add2(u64 a, u64 b) {
    u64 r; asm("add.rn.f32x2 %0, %1, %2;" : "=l"(r) : "l"(a), "l"(b)); return r;
}
__device__ __forceinline__ u64 fma2(u64 a, u64 b, u64 c) {
    u64 r; asm("fma.rn.f32x2 %0, %1, %2, %3;" : "=l"(r) : "l"(a), "l"(b), "l"(c)); return r;
}

#define C_LOG2E  1.4426950408889634f
#define C_LN2    0.6931471805599453f

__global__ __launch_bounds__(BLOCK_MAIN, 2)
void fused_kernel(const float* __restrict__ nlg, const float* __restrict__ slg,
                  const int* __restrict__ nlb,  const int* __restrict__ slb,
                  float* __restrict__ out)
{
    const int tid  = threadIdx.x;
    const int n    = tid & 127;                     // narrative class owned
    const int lane = blockIdx.x * 2 + (tid >> 7);   // row-processor id

    // packed constants
    const u64 cK    = pk2(C_LOG2E, C_LOG2E);        // +log2(e)
    const u64 cONE  = pk2(1.0f, 1.0f);
    const u64 cNEG1 = pk2(-1.0f, -1.0f);
    const u64 cLN2  = pk2(C_LN2, C_LN2);
    const u64 cM2885= pk2(-2.0f * C_LOG2E, -2.0f * C_LOG2E);

    u64 A2[4] = {0ull, 0ull, 0ull, 0ull};
    u64 sf2 = 0ull, Qs2 = 0ull;
    float Un = 0.f, Wn = 0.f, hier = 0.f, nfp = 0.f;
    int cn = 0, ca = 0, cb = 0;   // packed byte-lane counts (<=28 per byte, safe)

    const float4* sp  = (const float4*)slg + (size_t)lane * (NS / 4) + n * 2;
    const int4*   slp = (const int4*)slb   + (size_t)lane * (NS / 4) + n * 2;
    const float*  np  = nlg + (size_t)lane * NN + n;
    const int*    nbp = nlb + (size_t)lane * NN + n;
    const size_t  sstep = (size_t)LANES * (NS / 4);
    const size_t  nstep = (size_t)LANES * NN;

    // ---- prologue: load row `lane` ----
    float4 v0 = __ldcs(sp), v1 = __ldcs(sp + 1);
    int4   l0 = __ldcs(slp), l1 = __ldcs(slp + 1);
    float  xn = __ldcs(np);
    int    gi = __ldcs(nbp);

    for (int r = lane; r < B_ROWS; r += LANES) {
        // ---- prefetch next row, clamped-unconditional ----
        const bool  more = (r + LANES) < B_ROWS;
        const size_t sadv = more ? sstep : 0;
        const size_t nadv = more ? nstep : 0;
        sp += sadv; slp += sadv; np += nadv; nbp += nadv;
        float4 nv0 = __ldcs(sp), nv1 = __ldcs(sp + 1);
        int4   nl0 = __ldcs(slp), nl1 = __ldcs(slp + 1);
        float  nxn = __ldcs(np);
        int    ngi = __ldcs(nbp);

        float g = (float)gi;
        const u64 g2 = pk2(g, g);

        // ---- narrative element (no-abs form; inputs are N(0,1), safe) ----
        // en = exp(-x); spmn = softplus(-x); pn = sigmoid(x); (1-pn)^2 = (en*pn)^2
        float en   = exp2f(-C_LOG2E * xn);
        float un   = 1.0f + en;
        float spmn = C_LN2 * __log2f(un);
        float spn  = spmn + xn;
        float pn   = __fdividef(1.0f, un);
        float ompn = en * pn;
        nfp = fmaf(g * ompn * ompn, spmn, nfp);     // negate at end
        Un  = fmaf(g, spmn, Un);
        Wn  = fmaf(1.0f - g, spn, Wn);
        cn += gi;

        // ---- 8 subnarrative elements as 4 packed f32x2 pairs ----
        float xs[8] = { v0.x, v0.y, v0.z, v0.w, v1.x, v1.y, v1.z, v1.w };
        int   li[8] = { l0.x, l0.y, l0.z, l0.w, l1.x, l1.y, l1.z, l1.w };
        float mx = xs[0];
#pragma unroll
        for (int j = 0; j < 4; j++) {
            float x0 = xs[2*j], x1 = xs[2*j+1];
            u64 x2 = pk2(x0, x1);
            u64 t2 = mul2(x2, cK);                      // log2(e)*x
            float e0, e1; upk2(t2, e0, e1);
            e0 = exp2f(e0); e1 = exp2f(e1);             // exp(x)
            u64 u2 = add2(pk2(e0, e1), cONE);           // 1+exp(x)
            float L0, L1; upk2(u2, L0, L1);
            L0 = __log2f(L0); L1 = __log2f(L1);
            u64 spx2 = mul2(pk2(L0, L1), cLN2);         // softplus(x)
            u64 spm2 = fma2(x2, cNEG1, spx2);           // softplus(-x)
            u64 wt2  = mul2(spx2, cM2885);              // -2*log2(e)*spx
            float w0, w1; upk2(wt2, w0, w1);
            w0 = exp2f(w0); w1 = exp2f(w1);             // (1-p)^2
            float s0 = __int_as_float(li[2*j]   * 0x3f800000);
            float s1 = __int_as_float(li[2*j+1] * 0x3f800000);
            u64 s2  = pk2(s0, s1);
            u64 sw2 = mul2(pk2(w0, w1), s2);
            sf2 = fma2(sw2, spm2, sf2);                 // += s*(1-p)^2*spm ; negate at end
            u64 gs2 = mul2(g2, s2);
            A2[j] = fma2(gs2, spm2, A2[j]);             // += g*s*spm
            u64 gm2 = fma2(gs2, cNEG1, g2);             // g*(1-s)
            Qs2 = fma2(gm2, spx2, Qs2);                 // += g*(1-s)*spx
            mx = fmaxf(mx, fmaxf(x0, x1));
        }
        ca += li[0] + (li[1] << 8) + (li[2] << 16) + (li[3] << 24);
        cb += li[4] + (li[5] << 8) + (li[6] << 16) + (li[7] << 24);

        // ---- hierarchy: max(sigmoid)=sigmoid(max) ----
        float em = exp2f(-C_LOG2E * mx);
        float pm = __fdividef(1.0f, 1.0f + em);
        hier = fmaf(g, fmaxf(pm - pn, 0.0f), hier);

        // rotate double-buffer
        v0 = nv0; v1 = nv1; l0 = nl0; l1 = nl1; xn = nxn; gi = ngi;
    }

    // unpack packed accumulators
    float A[8];
#pragma unroll
    for (int j = 0; j < 4; j++) upk2(A2[j], A[2*j], A[2*j+1]);
    float q0, q1, f0, f1;
    upk2(Qs2, q0, q1); upk2(sf2, f0, f1);
    float Qs = q0 + q1;
    float sf = -(f0 + f1);
    float nf = -nfp;

    // ---------------- pair the two 128-lane halves in shared ----------------
    __shared__ float sh[128][17];    // odd stride -> conflict-free
    if (tid >= 128) {
        float* d = sh[tid - 128];
#pragma unroll
        for (int k = 0; k < 8; k++) d[k] = A[k];
        d[8] = Un; d[9] = Qs; d[10] = Wn; d[11] = hier; d[12] = nf; d[13] = sf;
        d[14] = __int_as_float(cn); d[15] = __int_as_float(ca); d[16] = __int_as_float(cb);
    }
    __syncthreads();

    const int shard = blockIdx.x & (NSHARD - 1);
    if (tid < 128) {
        float* d = sh[tid];
#pragma unroll
        for (int k = 0; k < 8; k++) A[k] += d[k];
        Un += d[8]; Qs += d[9]; Wn += d[10]; hier += d[11]; nf += d[12]; sf += d[13];
        cn += __float_as_int(d[14]);
        ca += __float_as_int(d[15]);
        cb += __float_as_int(d[16]);

        atomicAdd(&g_nU[shard][n], Un);
        atomicAdd(&g_nC[shard][n], (float)cn);
#pragma unroll
        for (int k = 0; k < 8; k++)
            atomicAdd(&g_sA[shard][n * 8 + k], A[k]);
#pragma unroll
        for (int k = 0; k < 4; k++) {
            atomicAdd(&g_sC[shard][n * 8 + k],     (float)((ca >> (8 * k)) & 255));
            atomicAdd(&g_sC[shard][n * 8 + 4 + k], (float)((cb >> (8 * k)) & 255));
        }
    }

    // scalar block-reduce over lower 128 threads (4 full warps)
    __shared__ float sw[5][4];
    if (tid < 128) {
#pragma unroll
        for (int o = 16; o; o >>= 1) {
            Qs   += __shfl_down_sync(0xffffffffu, Qs,   o);
            Wn   += __shfl_down_sync(0xffffffffu, Wn,   o);
            hier += __shfl_down_sync(0xffffffffu, hier, o);
            nf   += __shfl_down_sync(0xffffffffu, nf,   o);
            sf   += __shfl_down_sync(0xffffffffu, sf,   o);
        }
        if ((tid & 31) == 0) {
            int w = tid >> 5;
            sw[0][w] = Qs; sw[1][w] = Wn; sw[2][w] = hier; sw[3][w] = nf; sw[4][w] = sf;
        }
    }
    __syncthreads();
    if (tid < 5) {
        float v = sw[tid][0] + sw[tid][1] + sw[tid][2] + sw[tid][3];
        atomicAdd(&g_scl[tid], v);
    }

    // ---------------- last block finalizes and resets scratch ----------------
    __threadfence();
    __shared__ unsigned int s_last;
    if (tid == 0) s_last = (atomicAdd(&g_ctr, 1u) == (unsigned)(gridDim.x - 1)) ? 1u : 0u;
    __syncthreads();
    if (!s_last) return;
    __threadfence();

    double subAcc = 0.0, narrAcc = 0.0, valid = 0.0;
    for (int c = tid; c < NS; c += BLOCK_MAIN) {
        float Av = g_sA[0][c] + g_sA[1][c] + g_sA[2][c] + g_sA[3][c];
        float Cv = g_sC[0][c] + g_sC[1][c] + g_sC[2][c] + g_sC[3][c];
        float pw = fminf(fmaxf((16384.0f - Cv) / (Cv + 1e-6f), 1.0f), 50.0f);
        subAcc += (double)pw * (double)Av;
    }
    for (int c = tid; c < NN; c += BLOCK_MAIN) {
        float Uv = g_nU[0][c] + g_nU[1][c] + g_nU[2][c] + g_nU[3][c];
        float Cv = g_nC[0][c] + g_nC[1][c] + g_nC[2][c] + g_nC[3][c];
        float pw = fminf(fmaxf((16384.0f - Cv) / (Cv + 1e-6f), 1.0f), 50.0f);
        narrAcc += (double)pw * (double)Uv;
        valid   += (double)Cv;
    }
#pragma unroll
    for (int o = 16; o; o >>= 1) {
        subAcc  += __shfl_down_sync(0xffffffffu, subAcc,  o);
        narrAcc += __shfl_down_sync(0xffffffffu, narrAcc, o);
        valid   += __shfl_down_sync(0xffffffffu, valid,   o);
    }
    __shared__ double rd[24];
    if ((tid & 31) == 0) {
        int w = tid >> 5;   // 8 warps
        rd[w] = subAcc; rd[8 + w] = narrAcc; rd[16 + w] = valid;
    }
    __syncthreads();
    if (tid == 0) {
        double ss = 0.0, ns = 0.0, vv = 0.0;
        for (int i = 0; i < 8; i++) { ss += rd[i]; ns += rd[8 + i]; vv += rd[16 + i]; }
        double Qss = g_scl[0], Wns = g_scl[1];
        double hs = g_scl[2], nfs = g_scl[3], sfs = g_scl[4];

        double sub_total = ss + Qss;
        double narrative_loss = (ns + Wns) / (16384.0 * 128.0);
        double sub_loss = (vv > 0.0) ? (sub_total / 8.0) / fmax(vv, 1.0) : 0.0;
        double total = (narrative_loss - 0.1 * nfs / (16384.0 * 128.0))
                     + (sub_loss       - 0.1 * sfs / (16384.0 * 1024.0))
                     + 0.5 * hs / 16384.0;
        out[0] = (float)total;
    }
    __syncthreads();

    // reset scratch for the next graph replay
    for (int i = tid; i < NSHARD * NS; i += BLOCK_MAIN) {
        ((float*)g_sA)[i] = 0.f; ((float*)g_sC)[i] = 0.f;
    }
    for (int i = tid; i < NSHARD * NN; i += BLOCK_MAIN) {
        ((float*)g_nU)[i] = 0.f; ((float*)g_nC)[i] = 0.f;
    }
    if (tid < 8) g_scl[tid] = 0.f;
    if (tid == 0) g_ctr = 0u;
}

extern "C" void kernel_launch(void* const* d_in, const int* in_sizes, int n_in,
                              void* d_out, int out_size)
{
    const float* nlg = (const float*)d_in[0];   // narrative_logits [B,128]
    const float* slg = (const float*)d_in[1];   // subnarrative_logits [B,1024]
    const int*   nlb = (const int*)d_in[2];     // narrative_labels [B,128]
    const int*   slb = (const int*)d_in[3];     // subnarrative_labels [B,1024]
    (void)in_sizes; (void)n_in; (void)out_size;

    fused_kernel<<<GRID_MAIN, BLOCK_MAIN>>>(nlg, slg, nlb, slb, (float*)d_out);
}

// round 10
// speedup vs baseline: 1.1223x; 1.1223x over previous
#include <cuda_runtime.h>

#define B_ROWS 16384
#define NN     128
#define NS     1024
#define GRID_MAIN 444            // 3 blocks/SM * 148 SMs, single wave
#define BLOCK_MAIN 256
#define NSHARD 4

#define C_LOG2E  1.4426950408889634f
#define C_LN2    0.6931471805599453f

// ---------------- scratch (device globals; statically zero-initialized) ----------------
// Invariant: zero at entry of every kernel_launch; finalizing block resets.
__device__ float g_sA[NSHARD][NS];   // sum g*s*softplus(-x)  (sub, pw-weighted part)
__device__ float g_sC[NSHARD][NS];   // sum s (ungated column count)
__device__ float g_nU[NSHARD][NN];   // sum y*softplus(-x)    (narrative)
__device__ float g_nC[NSHARD][NN];   // sum y
__device__ float g_scl[8];           // 0=Qs 1=Wn 2=hier 3=nf 4=sf
__device__ unsigned int g_ctr;

__device__ __forceinline__ float softplus_f(float x) {
    // softplus(x) = max(x,0) + log1p(exp(-|x|)); EX2 + LG2
    float e = exp2f(-C_LOG2E * fabsf(x));
    float L = __log2f(1.0f + e);
    return fmaxf(x, 0.0f) + C_LN2 * L;
}

__global__ __launch_bounds__(BLOCK_MAIN, 3)
void fused_kernel(const float* __restrict__ nlg, const float* __restrict__ slg,
                  const int* __restrict__ nlb,  const int* __restrict__ slb,
                  float* __restrict__ out)
{
    const int tid = threadIdx.x;
    const int bid = blockIdx.x;
    const int c   = tid >> 1;               // narrative class (pair-shared)
    const float emf = (float)(1 - (tid & 1));  // 1.0 on even lane of each pair

    // one block per row; thread owns sub-quad [tid*4, tid*4+4)
    float A[4]  = {0.f, 0.f, 0.f, 0.f};
    float cs[4] = {0.f, 0.f, 0.f, 0.f};
    float Un = 0.f, cnf = 0.f, Qs = 0.f, Wn = 0.f, hier = 0.f, nfp = 0.f, sfp = 0.f;

    const float4* sp  = (const float4*)slg + (size_t)bid * (NS / 4) + tid;
    const int4*   slp = (const int4*)slb   + (size_t)bid * (NS / 4) + tid;
    const float*  np  = nlg + (size_t)bid * NN + c;
    const int*    nbp = nlb + (size_t)bid * NN + c;
    const size_t  sstep = (size_t)GRID_MAIN * (NS / 4);
    const size_t  nstep = (size_t)GRID_MAIN * NN;

    // ---- prologue: load row `bid` (fully coalesced: warp = 512B contiguous) ----
    float4 v = __ldcs(sp);
    int4   l = __ldcs(slp);
    float  xn = __ldcs(np);
    int    gi = __ldcs(nbp);

    for (int r = bid; r < B_ROWS; r += GRID_MAIN) {
        // ---- prefetch next row, clamped-unconditional ----
        const bool  more = (r + GRID_MAIN) < B_ROWS;
        const size_t sadv = more ? sstep : 0;
        const size_t nadv = more ? nstep : 0;
        sp += sadv; slp += sadv; np += nadv; nbp += nadv;
        float4 nv = __ldcs(sp);
        int4   nl = __ldcs(slp);
        float  nxn = __ldcs(np);
        int    ngi = __ldcs(nbp);

        float g  = (float)gi;
        float ge = g * emf;                               // even-gated g

        // ---- narrative element (pair-duplicated compute; even-gated accumulate) ----
        float e   = exp2f(-C_LOG2E * fabsf(xn));
        float t   = 1.0f + e;
        float q   = __fdividef(1.0f, t);                  // MUFU.RCP
        float spn = fmaxf(xn, 0.0f) + C_LN2 * __log2f(t);
        float spmn = spn - xn;                            // softplus(-x)
        bool  posn = (xn >= 0.0f);
        float pn   = posn ? q : e * q;                    // sigmoid(xn)
        float ompn = posn ? e * q : q;                    // 1 - sigmoid(xn)
        nfp = fmaf(ge * ompn * ompn, spmn, nfp);          // negate at end
        Un  = fmaf(ge, spmn, Un);
        Wn  = fmaf(emf - ge, spn, Wn);
        cnf += ge;

        // ---- 4 subnarrative elements of this quad ----
        float xs[4] = { v.x, v.y, v.z, v.w };
        int   li[4] = { l.x, l.y, l.z, l.w };
        float mx = xs[0];
#pragma unroll
        for (int k = 0; k < 4; k++) {
            float x   = xs[k];
            float s   = __int_as_float(li[k] * 0x3f800000);  // 0/1 -> 0.0f/1.0f
            float spx = softplus_f(x);
            float spm = spx - x;
            float w   = exp2f(-2.0f * C_LOG2E * spx);        // (1-p)^2
            sfp = fmaf(s * w, spm, sfp);                     // negate at end
            float gs = g * s;
            A[k] = fmaf(gs, spm, A[k]);
            Qs   = fmaf(g - gs, spx, Qs);                    // g*(1-s)*spx
            cs[k] += s;
            mx   = fmaxf(mx, x);
        }

        // ---- hierarchy: combine pair max via shfl; max(sigmoid)=sigmoid(max) ----
        float mxo = __shfl_xor_sync(0xffffffffu, mx, 1);
        float mxp = fmaxf(mx, mxo);
        float em2 = exp2f(-C_LOG2E * mxp);
        float pm  = __fdividef(1.0f, 1.0f + em2);
        hier = fmaf(ge, fmaxf(pm - pn, 0.0f), hier);

        // rotate double-buffer
        v = nv; l = nl; xn = nxn; gi = ngi;
    }

    // ---------------- per-class atomics (each class owned by 1 thread/block) ----------------
    const int shard = bid & (NSHARD - 1);
    const int cq = tid * 4;
#pragma unroll
    for (int k = 0; k < 4; k++) {
        atomicAdd(&g_sA[shard][cq + k], A[k]);
        atomicAdd(&g_sC[shard][cq + k], cs[k]);
    }
    if ((tid & 1) == 0) {
        atomicAdd(&g_nU[shard][c], Un);
        atomicAdd(&g_nC[shard][c], cnf);
    }

    // ---------------- block scalar reduce (all 8 warps) ----------------
    float nf = -nfp, sf = -sfp;
#pragma unroll
    for (int o = 16; o; o >>= 1) {
        Qs   += __shfl_down_sync(0xffffffffu, Qs,   o);
        Wn   += __shfl_down_sync(0xffffffffu, Wn,   o);
        hier += __shfl_down_sync(0xffffffffu, hier, o);
        nf   += __shfl_down_sync(0xffffffffu, nf,   o);
        sf   += __shfl_down_sync(0xffffffffu, sf,   o);
    }
    __shared__ float sw[5][8];
    if ((tid & 31) == 0) {
        int w = tid >> 5;
        sw[0][w] = Qs; sw[1][w] = Wn; sw[2][w] = hier; sw[3][w] = nf; sw[4][w] = sf;
    }
    __syncthreads();
    if (tid < 5) {
        float* p = sw[tid];
        float vsum = p[0] + p[1] + p[2] + p[3] + p[4] + p[5] + p[6] + p[7];
        atomicAdd(&g_scl[tid], vsum);
    }

    // ---------------- last block finalizes and resets scratch ----------------
    __threadfence();
    __shared__ unsigned int s_last;
    if (tid == 0) s_last = (atomicAdd(&g_ctr, 1u) == (unsigned)(gridDim.x - 1)) ? 1u : 0u;
    __syncthreads();
    if (!s_last) return;
    __threadfence();

    double subAcc = 0.0, narrAcc = 0.0, valid = 0.0;
    for (int cc = tid; cc < NS; cc += BLOCK_MAIN) {
        float Av = g_sA[0][cc] + g_sA[1][cc] + g_sA[2][cc] + g_sA[3][cc];
        float Cv = g_sC[0][cc] + g_sC[1][cc] + g_sC[2][cc] + g_sC[3][cc];
        float pw = fminf(fmaxf((16384.0f - Cv) / (Cv + 1e-6f), 1.0f), 50.0f);
        subAcc += (double)pw * (double)Av;
    }
    for (int cc = tid; cc < NN; cc += BLOCK_MAIN) {
        float Uv = g_nU[0][cc] + g_nU[1][cc] + g_nU[2][cc] + g_nU[3][cc];
        float Cv = g_nC[0][cc] + g_nC[1][cc] + g_nC[2][cc] + g_nC[3][cc];
        float pw = fminf(fmaxf((16384.0f - Cv) / (Cv + 1e-6f), 1.0f), 50.0f);
        narrAcc += (double)pw * (double)Uv;
        valid   += (double)Cv;
    }
#pragma unroll
    for (int o = 16; o; o >>= 1) {
        subAcc  += __shfl_down_sync(0xffffffffu, subAcc,  o);
        narrAcc += __shfl_down_sync(0xffffffffu, narrAcc, o);
        valid   += __shfl_down_sync(0xffffffffu, valid,   o);
    }
    __shared__ double rd[24];
    if ((tid & 31) == 0) {
        int w = tid >> 5;   // 8 warps
        rd[w] = subAcc; rd[8 + w] = narrAcc; rd[16 + w] = valid;
    }
    __syncthreads();
    if (tid == 0) {
        double ss = 0.0, ns = 0.0, vv = 0.0;
        for (int i = 0; i < 8; i++) { ss += rd[i]; ns += rd[8 + i]; vv += rd[16 + i]; }
        double Qss = g_scl[0], Wns = g_scl[1];
        double hs = g_scl[2], nfs = g_scl[3], sfs = g_scl[4];

        double sub_total = ss + Qss;
        double narrative_loss = (ns + Wns) / (16384.0 * 128.0);
        double sub_loss = (vv > 0.0) ? (sub_total / 8.0) / fmax(vv, 1.0) : 0.0;
        double total = (narrative_loss - 0.1 * nfs / (16384.0 * 128.0))
                     + (sub_loss       - 0.1 * sfs / (16384.0 * 1024.0))
                     + 0.5 * hs / 16384.0;
        out[0] = (float)total;
    }
    __syncthreads();

    // reset scratch for the next graph replay
    for (int i = tid; i < NSHARD * NS; i += BLOCK_MAIN) {
        ((float*)g_sA)[i] = 0.f; ((float*)g_sC)[i] = 0.f;
    }
    for (int i = tid; i < NSHARD * NN; i += BLOCK_MAIN) {
        ((float*)g_nU)[i] = 0.f; ((float*)g_nC)[i] = 0.f;
    }
    if (tid < 8) g_scl[tid] = 0.f;
    if (tid == 0) g_ctr = 0u;
}

extern "C" void kernel_launch(void* const* d_in, const int* in_sizes, int n_in,
                              void* d_out, int out_size)
{
    const float* nlg = (const float*)d_in[0];   // narrative_logits [B,128]
    const float* slg = (const float*)d_in[1];   // subnarrative_logits [B,1024]
    const int*   nlb = (const int*)d_in[2];     // narrative_labels [B,128]
    const int*   slb = (const int*)d_in[3];     // subnarrative_labels [B,1024]
    (void)in_sizes; (void)n_in; (void)out_size;

    fused_kernel<<<GRID_MAIN, BLOCK_MAIN>>>(nlg, slg, nlb, slb, (float*)d_out);
}

// round 11
// speedup vs baseline: 1.3540x; 1.2065x over previous
#include <cuda_runtime.h>

#define B_ROWS 16384
#define NPAIRS (B_ROWS / 2)      // 8192 row-pairs
#define NN     128
#define NS     1024
#define GRID_MAIN 296            // 2 blocks/SM * 148 SMs
#define BLOCK_MAIN 256
#define NSHARD 4

#define C_LOG2E  1.4426950408889634f
#define C_LN2    0.6931471805599453f

// ---------------- scratch (device globals; statically zero-initialized) ----------------
// Invariant: zero at entry of every kernel_launch; finalizing block resets.
__device__ float g_sA[NSHARD][NS];   // sum g*s*softplus(-x)  (sub, pw-weighted part)
__device__ float g_sC[NSHARD][NS];   // sum s (ungated column count)
__device__ float g_nU[NSHARD][NN];   // sum y*softplus(-x)    (narrative)
__device__ float g_nC[NSHARD][NN];   // sum y
__device__ float g_scl[8];           // 0=Qs 1=Wn 2=hier 3=nf 4=sf
__device__ unsigned int g_ctr;

__device__ __forceinline__ float softplus_f(float x) {
    // softplus(x) = max(x,0) + log1p(exp(-|x|)); EX2 + LG2
    float e = exp2f(-C_LOG2E * fabsf(x));
    float L = __log2f(1.0f + e);
    return fmaxf(x, 0.0f) + C_LN2 * L;
}

__global__ __launch_bounds__(BLOCK_MAIN, 2)
void fused_kernel(const float* __restrict__ nlg, const float* __restrict__ slg,
                  const int* __restrict__ nlb,  const int* __restrict__ slb,
                  float* __restrict__ out)
{
    const int tid = threadIdx.x;
    const int bid = blockIdx.x;
    const int par = tid & 1;                 // 0: narrative of row a, 1: row b
    const int c   = tid >> 1;                // narrative class for this thread

    // thread owns sub-quad [tid*4, tid*4+4) of BOTH rows of each pair
    float A[4]  = {0.f, 0.f, 0.f, 0.f};
    float cs[4] = {0.f, 0.f, 0.f, 0.f};
    float Un = 0.f, cnf = 0.f, Qs = 0.f, Wn = 0.f, hier = 0.f, nfp = 0.f, sfp = 0.f;

    // pair p -> rows (2p, 2p+1); fully coalesced: warp = 512B contiguous per load
    const float4* sp  = (const float4*)slg + (size_t)bid * 2 * (NS / 4) + tid;
    const int4*   slp = (const int4*)slb   + (size_t)bid * 2 * (NS / 4) + tid;
    const float*  np  = nlg + ((size_t)bid * 2 + par) * NN + c;
    const int*    nbp = nlb + ((size_t)bid * 2 + par) * NN + c;
    const size_t  sstep = (size_t)GRID_MAIN * 2 * (NS / 4);
    const size_t  nstep = (size_t)GRID_MAIN * 2 * NN;

    // ---- prologue: load pair `bid` ----
    float4 vA = __ldcs(sp),        vB = __ldcs(sp + (NS / 4));
    int4   lA = __ldcs(slp),       lB = __ldcs(slp + (NS / 4));
    float  xn = __ldcs(np);
    int    gi = __ldcs(nbp);

    for (int p = bid; p < NPAIRS; p += GRID_MAIN) {
        // ---- prefetch next pair, clamped-unconditional ----
        const bool  more = (p + GRID_MAIN) < NPAIRS;
        const size_t sadv = more ? sstep : 0;
        const size_t nadv = more ? nstep : 0;
        sp += sadv; slp += sadv; np += nadv; nbp += nadv;
        float4 nvA = __ldcs(sp),  nvB = __ldcs(sp + (NS / 4));
        int4   nlA = __ldcs(slp), nlB = __ldcs(slp + (NS / 4));
        float  nxn = __ldcs(np);
        int    ngi = __ldcs(nbp);

        // ---- narrative element (own row only; zero duplication) ----
        float g_own = (float)gi;
        float e   = exp2f(-C_LOG2E * fabsf(xn));
        float t   = 1.0f + e;
        float q   = __fdividef(1.0f, t);                  // MUFU.RCP
        float spn = fmaxf(xn, 0.0f) + C_LN2 * __log2f(t);
        float spmn = spn - xn;                            // softplus(-x)
        bool  posn = (xn >= 0.0f);
        float pn   = posn ? q : e * q;                    // sigmoid(xn)
        float ompn = posn ? e * q : q;                    // 1 - sigmoid(xn)
        nfp = fmaf(g_own * ompn * ompn, spmn, nfp);       // negate at end
        Un  = fmaf(g_own, spmn, Un);
        Wn  = fmaf(1.0f - g_own, spn, Wn);
        cnf += g_own;

        // exchange narrative gates within the pair
        float g_oth = __shfl_xor_sync(0xffffffffu, g_own, 1);
        float ga = par ? g_oth : g_own;   // gate for row a
        float gb = par ? g_own : g_oth;   // gate for row b

        // ---- 4 sub elements of row a + 4 of row b (independent chains, 2x ILP) ----
        float xa[4] = { vA.x, vA.y, vA.z, vA.w };
        int   ia[4] = { lA.x, lA.y, lA.z, lA.w };
        float xb[4] = { vB.x, vB.y, vB.z, vB.w };
        int   ib[4] = { lB.x, lB.y, lB.z, lB.w };
        float mxA = xa[0], mxB = xb[0];
#pragma unroll
        for (int k = 0; k < 4; k++) {
            // row a
            float x0   = xa[k];
            float s0   = __int_as_float(ia[k] * 0x3f800000);
            float spx0 = softplus_f(x0);
            float spm0 = spx0 - x0;
            float w0   = exp2f(-2.0f * C_LOG2E * spx0);
            sfp = fmaf(s0 * w0, spm0, sfp);
            float gs0 = ga * s0;
            A[k] = fmaf(gs0, spm0, A[k]);
            Qs   = fmaf(ga - gs0, spx0, Qs);
            cs[k] += s0;
            mxA  = fmaxf(mxA, x0);
            // row b
            float x1   = xb[k];
            float s1   = __int_as_float(ib[k] * 0x3f800000);
            float spx1 = softplus_f(x1);
            float spm1 = spx1 - x1;
            float w1   = exp2f(-2.0f * C_LOG2E * spx1);
            sfp = fmaf(s1 * w1, spm1, sfp);
            float gs1 = gb * s1;
            A[k] = fmaf(gs1, spm1, A[k]);
            Qs   = fmaf(gb - gs1, spx1, Qs);
            cs[k] += s1;
            mxB  = fmaxf(mxB, x1);
        }

        // ---- hierarchy: class max over both quads via pair shfl; own row only ----
        float fullA = fmaxf(mxA, __shfl_xor_sync(0xffffffffu, mxA, 1));
        float fullB = fmaxf(mxB, __shfl_xor_sync(0xffffffffu, mxB, 1));
        float fullO = par ? fullB : fullA;
        float em2 = exp2f(-C_LOG2E * fullO);
        float pm  = __fdividef(1.0f, 1.0f + em2);
        hier = fmaf(g_own, fmaxf(pm - pn, 0.0f), hier);

        // rotate double-buffer
        vA = nvA; vB = nvB; lA = nlA; lB = nlB; xn = nxn; gi = ngi;
    }

    // ---------------- per-class atomics (thread owns its quad; both parities own class c) ----------------
    const int shard = bid & (NSHARD - 1);
    const int cq = tid * 4;
#pragma unroll
    for (int k = 0; k < 4; k++) {
        atomicAdd(&g_sA[shard][cq + k], A[k]);
        atomicAdd(&g_sC[shard][cq + k], cs[k]);
    }
    atomicAdd(&g_nU[shard][c], Un);
    atomicAdd(&g_nC[shard][c], cnf);

    // ---------------- block scalar reduce (all 8 warps) ----------------
    float nf = -nfp, sf = -sfp;
#pragma unroll
    for (int o = 16; o; o >>= 1) {
        Qs   += __shfl_down_sync(0xffffffffu, Qs,   o);
        Wn   += __shfl_down_sync(0xffffffffu, Wn,   o);
        hier += __shfl_down_sync(0xffffffffu, hier, o);
        nf   += __shfl_down_sync(0xffffffffu, nf,   o);
        sf   += __shfl_down_sync(0xffffffffu, sf,   o);
    }
    __shared__ float sw[5][8];
    if ((tid & 31) == 0) {
        int w = tid >> 5;
        sw[0][w] = Qs; sw[1][w] = Wn; sw[2][w] = hier; sw[3][w] = nf; sw[4][w] = sf;
    }
    __syncthreads();
    if (tid < 5) {
        float* pp = sw[tid];
        float vsum = pp[0] + pp[1] + pp[2] + pp[3] + pp[4] + pp[5] + pp[6] + pp[7];
        atomicAdd(&g_scl[tid], vsum);
    }

    // ---------------- last block finalizes and resets scratch ----------------
    __threadfence();
    __shared__ unsigned int s_last;
    if (tid == 0) s_last = (atomicAdd(&g_ctr, 1u) == (unsigned)(gridDim.x - 1)) ? 1u : 0u;
    __syncthreads();
    if (!s_last) return;
    __threadfence();

    double subAcc = 0.0, narrAcc = 0.0, valid = 0.0;
    for (int cc = tid; cc < NS; cc += BLOCK_MAIN) {
        float Av = g_sA[0][cc] + g_sA[1][cc] + g_sA[2][cc] + g_sA[3][cc];
        float Cv = g_sC[0][cc] + g_sC[1][cc] + g_sC[2][cc] + g_sC[3][cc];
        float pw = fminf(fmaxf((16384.0f - Cv) / (Cv + 1e-6f), 1.0f), 50.0f);
        subAcc += (double)pw * (double)Av;
    }
    for (int cc = tid; cc < NN; cc += BLOCK_MAIN) {
        float Uv = g_nU[0][cc] + g_nU[1][cc] + g_nU[2][cc] + g_nU[3][cc];
        float Cv = g_nC[0][cc] + g_nC[1][cc] + g_nC[2][cc] + g_nC[3][cc];
        float pw = fminf(fmaxf((16384.0f - Cv) / (Cv + 1e-6f), 1.0f), 50.0f);
        narrAcc += (double)pw * (double)Uv;
        valid   += (double)Cv;
    }
#pragma unroll
    for (int o = 16; o; o >>= 1) {
        subAcc  += __shfl_down_sync(0xffffffffu, subAcc,  o);
        narrAcc += __shfl_down_sync(0xffffffffu, narrAcc, o);
        valid   += __shfl_down_sync(0xffffffffu, valid,   o);
    }
    __shared__ double rd[24];
    if ((tid & 31) == 0) {
        int w = tid >> 5;   // 8 warps
        rd[w] = subAcc; rd[8 + w] = narrAcc; rd[16 + w] = valid;
    }
    __syncthreads();
    if (tid == 0) {
        double ss = 0.0, ns = 0.0, vv = 0.0;
        for (int i = 0; i < 8; i++) { ss += rd[i]; ns += rd[8 + i]; vv += rd[16 + i]; }
        double Qss = g_scl[0], Wns = g_scl[1];
        double hs = g_scl[2], nfs = g_scl[3], sfs = g_scl[4];

        double sub_total = ss + Qss;
        double narrative_loss = (ns + Wns) / (16384.0 * 128.0);
        double sub_loss = (vv > 0.0) ? (sub_total / 8.0) / fmax(vv, 1.0) : 0.0;
        double total = (narrative_loss - 0.1 * nfs / (16384.0 * 128.0))
                     + (sub_loss       - 0.1 * sfs / (16384.0 * 1024.0))
                     + 0.5 * hs / 16384.0;
        out[0] = (float)total;
    }
    __syncthreads();

    // reset scratch for the next graph replay
    for (int i = tid; i < NSHARD * NS; i += BLOCK_MAIN) {
        ((float*)g_sA)[i] = 0.f; ((float*)g_sC)[i] = 0.f;
    }
    for (int i = tid; i < NSHARD * NN; i += BLOCK_MAIN) {
        ((float*)g_nU)[i] = 0.f; ((float*)g_nC)[i] = 0.f;
    }
    if (tid < 8) g_scl[tid] = 0.f;
    if (tid == 0) g_ctr = 0u;
}

extern "C" void kernel_launch(void* const* d_in, const int* in_sizes, int n_in,
                              void* d_out, int out_size)
{
    const float* nlg = (const float*)d_in[0];   // narrative_logits [B,128]
    const float* slg = (const float*)d_in[1];   // subnarrative_logits [B,1024]
    const int*   nlb = (const int*)d_in[2];     // narrative_labels [B,128]
    const int*   slb = (const int*)d_in[3];     // subnarrative_labels [B,1024]
    (void)in_sizes; (void)n_in; (void)out_size;

    fused_kernel<<<GRID_MAIN, BLOCK_MAIN>>>(nlg, slg, nlb, slb, (float*)d_out);
}